// round 1
// baseline (speedup 1.0000x reference)
#include <cuda_runtime.h>
#include <math.h>

// Problem constants
#define B_ 16
#define T_ 1000
#define FEAT_ 771
#define H_ 512
#define KN_ 9
#define IND_ 257
#define M_ (B_ * T_)          // 16000

// Scratch (device globals; allocation is banned)
__device__ float g_x0[(size_t)T_ * B_ * H_];        // 32.8 MB  (time-major (T,B,H))
__device__ float g_x1[(size_t)T_ * B_ * H_];        // 32.8 MB
__device__ float g_U[(size_t)M_ * 3 * H_];          // 98.3 MB  (rows m = t*B+b)
__device__ float g_conv[(size_t)B_ * KN_ * T_ * H_];// 294.9 MB (b,kn,t,h)
__device__ float g_pool[(size_t)M_ * KN_ * H_];     // 294.9 MB ((b,t),kn,h)

__device__ __forceinline__ float sigmoidf_(float x) {
    return 1.0f / (1.0f + __expf(-x));
}

// ---------------------------------------------------------------------------
// Register-blocked SGEMM, 128x128 tile, BK=16, 256 threads, 8x8 per thread.
// MODE 0: A=inputs(param) [M x 771], B=W_in [771 x 512], C=g_x0 with
//         permuted store x0[(t*B+b)*H+n] = tanh(acc + b_in[n])
// MODE 1: A=(LSEL? g_x1 : g_x0) [M x 512] (rows already t*B+b),
//         B=W_rnn[l] [512 x 1536], C=g_U raw
// MODE 2: A=g_pool [M x 4608] (k = kn*512+h), B=W_out with row remap
//         row=(h*9+kn), cols 257..513 only; C=out(param):
//         out[m*257+n] = sigmoid(acc + b_out[257+n]) * inputs[m*771+257+n]
// ---------------------------------------------------------------------------
template<int MODE, int LSEL>
__global__ void __launch_bounds__(256, 2) gemm_kernel(
    const float* __restrict__ Aparam, const float* __restrict__ Bmat,
    const float* __restrict__ bias, const float* __restrict__ extra,
    float* __restrict__ Cparam, int M, int N, int K, int ldb)
{
    const float* A;
    float* C;
    if (MODE == 0)      { A = Aparam;                 C = g_x0;   }
    else if (MODE == 1) { A = LSEL ? g_x1 : g_x0;     C = g_U;    }
    else                { A = g_pool;                 C = Cparam; }

    __shared__ float As[16][132];   // [k][m], padded (row = 528B, 16B aligned)
    __shared__ float Bs[16][128];   // [k][n]

    const int tid = threadIdx.x;
    const int bm = blockIdx.y * 128;
    const int bn = blockIdx.x * 128;
    const int tx = tid & 15;        // n direction
    const int ty = tid >> 4;        // m direction

    float acc[8][8];
    #pragma unroll
    for (int i = 0; i < 8; i++)
        #pragma unroll
        for (int j = 0; j < 8; j++) acc[i][j] = 0.f;

    for (int k0 = 0; k0 < K; k0 += 16) {
        // Load A tile: 128 x 16
        #pragma unroll
        for (int i = 0; i < 8; i++) {
            int idx = tid + i * 256;
            int k = idx & 15;
            int m = idx >> 4;
            int kg = k0 + k;
            float v = 0.f;
            if (kg < K) v = A[(size_t)(bm + m) * K + kg];
            As[k][m] = v;
        }
        // Load B tile: 16 x 128
        #pragma unroll
        for (int i = 0; i < 8; i++) {
            int idx = tid + i * 256;
            int n = idx & 127;
            int k = idx >> 7;
            int kg = k0 + k;
            int ng = bn + n;
            float v = 0.f;
            if (MODE == 2) {
                if (ng < N) {                 // K=4608 is a multiple of 16
                    int kn = kg >> 9;         // / 512
                    int hh = kg & 511;
                    v = Bmat[(size_t)(hh * KN_ + kn) * ldb + IND_ + ng];
                }
            } else {
                if (kg < K && ng < N) v = Bmat[(size_t)kg * ldb + ng];
            }
            Bs[k][n] = v;
        }
        __syncthreads();

        #pragma unroll
        for (int kk = 0; kk < 16; kk++) {
            float a[8], b[8];
            const float4* ar = reinterpret_cast<const float4*>(&As[kk][0]);
            float4 a0 = ar[ty * 2], a1 = ar[ty * 2 + 1];
            a[0]=a0.x; a[1]=a0.y; a[2]=a0.z; a[3]=a0.w;
            a[4]=a1.x; a[5]=a1.y; a[6]=a1.z; a[7]=a1.w;
            const float4* br = reinterpret_cast<const float4*>(&Bs[kk][0]);
            float4 b0 = br[tx * 2], b1 = br[tx * 2 + 1];
            b[0]=b0.x; b[1]=b0.y; b[2]=b0.z; b[3]=b0.w;
            b[4]=b1.x; b[5]=b1.y; b[6]=b1.z; b[7]=b1.w;
            #pragma unroll
            for (int i = 0; i < 8; i++)
                #pragma unroll
                for (int j = 0; j < 8; j++)
                    acc[i][j] = fmaf(a[i], b[j], acc[i][j]);
        }
        __syncthreads();
    }

    // Epilogue (M = 16000 is a multiple of 128, so no m guard needed)
    #pragma unroll
    for (int i = 0; i < 8; i++) {
        int m = bm + ty * 8 + i;
        #pragma unroll
        for (int j = 0; j < 8; j++) {
            int n = bn + tx * 8 + j;
            if (n >= N) continue;
            float v = acc[i][j];
            if (MODE == 0) {
                int bb = m / T_, tt = m % T_;
                C[((size_t)tt * B_ + bb) * H_ + n] = tanhf(v + bias[n]);
            } else if (MODE == 1) {
                C[(size_t)m * N + n] = v;
            } else {
                float s = sigmoidf_(v + bias[n]);
                C[(size_t)m * IND_ + n] = s * extra[(size_t)m * FEAT_ + IND_ + n];
            }
        }
    }
}

// ---------------------------------------------------------------------------
// SRU sequential scan. One thread per (b, h) chain; 8192 chains, T=1000 steps.
// Reads g_U (xt/fp/rp) and layer input x, writes layer output x.
// ---------------------------------------------------------------------------
template<int L>
__global__ void sru_scan(const float* __restrict__ v, const float* __restrict__ bb)
{
    const float* xin  = (L == 0) ? g_x0 : g_x1;
    float*       xout = (L == 0) ? g_x1 : g_x0;
    int idx = blockIdx.x * blockDim.x + threadIdx.x;
    if (idx >= B_ * H_) return;
    int b = idx / H_;
    int h = idx % H_;
    float vf = v[h],  vr = v[H_ + h];
    float bf = bb[h], br = bb[H_ + h];
    float c = 0.f;
    const float* Ur = g_U + (size_t)b * 3 * H_ + h;
    const float* xr = xin + (size_t)b * H_ + h;
    float*       xo = xout + (size_t)b * H_ + h;
    #pragma unroll 4
    for (int t = 0; t < T_; t++) {
        float xt = Ur[0];
        float fp = Ur[H_];
        float rp = Ur[2 * H_];
        float xi = xr[0];
        float f  = sigmoidf_(fp + vf * c + bf);
        float cn = f * c + (1.f - f) * xt;
        float r  = sigmoidf_(rp + vr * c + br);
        xo[0] = r * cn + (1.f - r) * xi;
        c = cn;
        Ur += B_ * 3 * H_;
        xr += B_ * H_;
        xo += B_ * H_;
    }
}

// ---------------------------------------------------------------------------
// Conv2d 6x6, in_ch=1, out_ch=9, pad (top/left 3, bottom/right 2), + bias, tanh.
// Input: g_x0 in (T,B,H). Output: g_conv in (b,kn,t,h). One thread per output.
// ---------------------------------------------------------------------------
__global__ void conv_kernel(const float* __restrict__ ck, const float* __restrict__ cb)
{
    __shared__ float sk[KN_ * 36];
    for (int i = threadIdx.x; i < KN_ * 36; i += blockDim.x) sk[i] = ck[i];
    __syncthreads();
    int idx = blockIdx.x * blockDim.x + threadIdx.x;
    const int total = B_ * KN_ * T_ * H_;
    if (idx >= total) return;
    int h  = idx & (H_ - 1);
    int t  = (idx / H_) % T_;
    int kn = (idx / (H_ * T_)) % KN_;
    int b  = idx / (H_ * T_ * KN_);
    const float* w = &sk[kn * 36];
    float s = 0.f;
    int ilo = (t >= 3) ? 0 : (3 - t);
    int ihi = min(6, T_ + 3 - t);
    int jlo = (h >= 3) ? 0 : (3 - h);
    int jhi = min(6, H_ + 3 - h);
    for (int i = ilo; i < ihi; i++) {
        const float* xr = &g_x0[((size_t)(t + i - 3) * B_ + b) * H_ + (h - 3)];
        const float* wr = &w[i * 6];
        for (int j = jlo; j < jhi; j++) s += xr[j] * wr[j];
    }
    g_conv[idx] = tanhf(s + cb[kn]);
}

// ---------------------------------------------------------------------------
// MaxPool 3x3, stride 1, pad 1 over (t, h); also permutes layout:
// in g_conv (b,kn,t,h) -> out g_pool ((b,t),kn,h) so the output-GEMM K index
// is k = kn*512 + h (W_out row remap happens in the GEMM B-load).
// ---------------------------------------------------------------------------
__global__ void pool_kernel()
{
    int idx = blockIdx.x * blockDim.x + threadIdx.x;
    const int total = B_ * T_ * KN_ * H_;
    if (idx >= total) return;
    int h  = idx & (H_ - 1);
    int kn = (idx / H_) % KN_;
    int t  = (idx / (H_ * KN_)) % T_;
    int b  = idx / (H_ * KN_ * T_);
    const float* base = &g_conv[(size_t)(b * KN_ + kn) * T_ * H_];
    float m = -1e30f;
    int t0 = max(t - 1, 0), t1 = min(t + 1, T_ - 1);
    int h0 = max(h - 1, 0), h1 = min(h + 1, H_ - 1);
    for (int tt = t0; tt <= t1; tt++)
        for (int hh = h0; hh <= h1; hh++)
            m = fmaxf(m, base[(size_t)tt * H_ + hh]);
    g_pool[idx] = m;
}

// ---------------------------------------------------------------------------
extern "C" void kernel_launch(void* const* d_in, const int* in_sizes, int n_in,
                              void* d_out, int out_size)
{
    (void)in_sizes; (void)n_in; (void)out_size;
    const float* inputs = (const float*)d_in[0];
    const float* W_in   = (const float*)d_in[1];
    const float* b_in   = (const float*)d_in[2];
    const float* W_rnn  = (const float*)d_in[3];
    const float* v_rnn  = (const float*)d_in[4];
    const float* b_rnn  = (const float*)d_in[5];
    const float* conv_k = (const float*)d_in[6];
    const float* conv_b = (const float*)d_in[7];
    const float* W_out  = (const float*)d_in[8];
    const float* b_out  = (const float*)d_in[9];
    float* out = (float*)d_out;

    // Input layer: tanh(inputs @ W_in + b_in), stored time-major into g_x0
    gemm_kernel<0,0><<<dim3(4, 125), 256>>>(inputs, W_in, b_in, nullptr, nullptr,
                                            M_, H_, FEAT_, H_);
    // SRU layer 0: U = x0 @ W_rnn[0]; scan -> g_x1
    gemm_kernel<1,0><<<dim3(12, 125), 256>>>(nullptr, W_rnn, nullptr, nullptr, nullptr,
                                             M_, 3 * H_, H_, 3 * H_);
    sru_scan<0><<<64, 128>>>(v_rnn, b_rnn);
    // SRU layer 1: U = x1 @ W_rnn[1]; scan -> g_x0
    gemm_kernel<1,1><<<dim3(12, 125), 256>>>(nullptr, W_rnn + (size_t)H_ * 3 * H_,
                                             nullptr, nullptr, nullptr,
                                             M_, 3 * H_, H_, 3 * H_);
    sru_scan<1><<<64, 128>>>(v_rnn + 2 * H_, b_rnn + 2 * H_);
    // Conv + tanh
    conv_kernel<<<(B_ * KN_ * T_ * H_ + 255) / 256, 256>>>(conv_k, conv_b);
    // MaxPool + layout permute
    pool_kernel<<<(B_ * T_ * KN_ * H_ + 255) / 256, 256>>>();
    // Output GEMM (only the 257 center columns) + sigmoid * inputs
    gemm_kernel<2,0><<<dim3(3, 125), 256>>>(nullptr, W_out, b_out + IND_, inputs, out,
                                            M_, IND_, KN_ * H_, FEAT_);
}

// round 3
// speedup vs baseline: 1.4858x; 1.4858x over previous
#include <cuda_runtime.h>
#include <cuda_bf16.h>
#include <math.h>
#include <stdint.h>

// Problem constants
#define B_ 16
#define T_ 1000
#define FEAT_ 771
#define H_ 512
#define KN_ 9
#define IND_ 257
#define M_ (B_ * T_)          // 16000

// Scratch (device globals; allocation is banned)
__device__ float g_x0[(size_t)T_ * B_ * H_];        // (T,B,H)
__device__ float g_x1[(size_t)T_ * B_ * H_];
__device__ float g_U[(size_t)M_ * 3 * H_];          // rows m = t*B+b
__device__ float g_conv[(size_t)B_ * KN_ * T_ * H_];
__device__ float g_pool[(size_t)M_ * KN_ * H_];     // ((b,t),kn,h)

__device__ __forceinline__ float sigmoidf_(float x) {
    return 1.0f / (1.0f + __expf(-x));
}

__device__ __forceinline__ uint32_t smem_u32(const void* p) {
    uint32_t a;
    asm("{ .reg .u64 t; cvta.to.shared.u64 t, %1; cvt.u32.u64 %0, t; }"
        : "=r"(a) : "l"(p));
    return a;
}

// ===========================================================================
// Warp-MMA bf16 helpers (sm_80 baseline PTX — compiles at compute_103)
// ===========================================================================
#define LDSM4(r, addr) \
    asm volatile("ldmatrix.sync.aligned.m8n8.x4.shared.b16 {%0,%1,%2,%3}, [%4];" \
        : "=r"((r)[0]), "=r"((r)[1]), "=r"((r)[2]), "=r"((r)[3]) : "r"(addr))
#define LDSM4T(r, addr) \
    asm volatile("ldmatrix.sync.aligned.m8n8.x4.trans.shared.b16 {%0,%1,%2,%3}, [%4];" \
        : "=r"((r)[0]), "=r"((r)[1]), "=r"((r)[2]), "=r"((r)[3]) : "r"(addr))
#define MMA16816(c, a, b) \
    asm volatile("mma.sync.aligned.m16n8k16.row.col.f32.bf16.bf16.f32 " \
        "{%0,%1,%2,%3}, {%4,%5,%6,%7}, {%8,%9}, {%0,%1,%2,%3};" \
        : "+f"((c)[0]), "+f"((c)[1]), "+f"((c)[2]), "+f"((c)[3]) \
        : "r"((a)[0]), "r"((a)[1]), "r"((a)[2]), "r"((a)[3]), \
          "r"((b)[0]), "r"((b)[1]))

// pack two floats as bf16x2 {lo, hi}
__device__ __forceinline__ uint32_t pack_bf(float lo, float hi) {
    uint32_t r;
    asm("cvt.rn.bf16x2.f32 %0, %1, %2;" : "=r"(r) : "f"(hi), "f"(lo));
    return r;
}
// hi = bf16(x) as float; lo = x - hi
__device__ __forceinline__ void split_hl(float x, float& h, float& l) {
    h = __bfloat162float(__float2bfloat16_rn(x));
    l = x - h;
}

// Smem layout (per stage): Ah[128][40h] 80B rows, Al, Bh[32][136h] 272B rows, Bl
#define AH_O 0
#define AL_O 10240
#define BH_O 20480
#define BL_O 29184
#define STG_SZ 37888
#define MMA_SMEM (2 * STG_SZ)   // 75776 bytes

// ===========================================================================
// bf16 split mma.sync GEMM. 128x128 CTA tile, 256 thr (8 warps 4x2), BK=32.
// D = Ah*Bh + Ah*Bl + Al*Bh in fp32 accumulators (error ~4e-6).
// MODE 0: A=inputs [M,771], B=W_in [771,512] -> g_x0 tanh + time-major permute
// MODE 1: A=g_x0/g_x1 [M,512], B=W_rnn[l] [512,1536] -> g_U raw
// MODE 2: A=g_pool [M,4608], B=W_out rows remapped (h*9+kn), cols 257..513
//         -> out = sigmoid(acc+bias)*inputs center slice
// ===========================================================================
template<int MODE>
__device__ __forceinline__ void load_A(const float* __restrict__ A, int lda, int K,
                                       int bm, int k0, int tid, float v[2][8]) {
    #pragma unroll
    for (int it = 0; it < 2; it++) {
        int slot = tid + it * 256;
        int m = slot >> 2;
        int kg = (slot & 3) * 8;
        const float* src = A + (size_t)(bm + m) * lda + k0 + kg;
        if (MODE == 0) {
            #pragma unroll
            for (int j = 0; j < 8; j++)
                v[it][j] = (k0 + kg + j < K) ? src[j] : 0.f;
        } else {
            float4 p0 = *(const float4*)(src);
            float4 p1 = *(const float4*)(src + 4);
            v[it][0] = p0.x; v[it][1] = p0.y; v[it][2] = p0.z; v[it][3] = p0.w;
            v[it][4] = p1.x; v[it][5] = p1.y; v[it][6] = p1.z; v[it][7] = p1.w;
        }
    }
}

template<int MODE>
__device__ __forceinline__ void load_B(const float* __restrict__ Bm, int ldb, int K,
                                       int N, int bn, int k0, int tid, float v[2][8]) {
    #pragma unroll
    for (int it = 0; it < 2; it++) {
        int slot = tid + it * 256;
        int k = slot >> 4;
        int n0 = (slot & 15) * 8;
        int kg = k0 + k;
        if (MODE == 2) {
            int kn = kg >> 9, hh = kg & 511;
            const float* src = Bm + (size_t)(hh * KN_ + kn) * ldb + IND_ + bn + n0;
            #pragma unroll
            for (int j = 0; j < 8; j++)
                v[it][j] = (bn + n0 + j < N) ? src[j] : 0.f;
        } else {
            const float* src = Bm + (size_t)kg * ldb + bn + n0;
            if (kg < K) {
                float4 p0 = *(const float4*)(src);
                float4 p1 = *(const float4*)(src + 4);
                v[it][0] = p0.x; v[it][1] = p0.y; v[it][2] = p0.z; v[it][3] = p0.w;
                v[it][4] = p1.x; v[it][5] = p1.y; v[it][6] = p1.z; v[it][7] = p1.w;
            } else {
                #pragma unroll
                for (int j = 0; j < 8; j++) v[it][j] = 0.f;
            }
        }
    }
}

__device__ __forceinline__ void store_stage(char* sbuf, int tid,
                                            float va[2][8], float vb[2][8]) {
    #pragma unroll
    for (int it = 0; it < 2; it++) {
        int slot = tid + it * 256;
        int m = slot >> 2;
        int kg = (slot & 3) * 8;
        float h[8], l[8];
        #pragma unroll
        for (int j = 0; j < 8; j++) split_hl(va[it][j], h[j], l[j]);
        uint4 hv = make_uint4(pack_bf(h[0],h[1]), pack_bf(h[2],h[3]),
                              pack_bf(h[4],h[5]), pack_bf(h[6],h[7]));
        uint4 lv = make_uint4(pack_bf(l[0],l[1]), pack_bf(l[2],l[3]),
                              pack_bf(l[4],l[5]), pack_bf(l[6],l[7]));
        int off = m * 80 + kg * 2;
        *(uint4*)(sbuf + AH_O + off) = hv;
        *(uint4*)(sbuf + AL_O + off) = lv;
    }
    #pragma unroll
    for (int it = 0; it < 2; it++) {
        int slot = tid + it * 256;
        int k = slot >> 4;
        int n0 = (slot & 15) * 8;
        float h[8], l[8];
        #pragma unroll
        for (int j = 0; j < 8; j++) split_hl(vb[it][j], h[j], l[j]);
        uint4 hv = make_uint4(pack_bf(h[0],h[1]), pack_bf(h[2],h[3]),
                              pack_bf(h[4],h[5]), pack_bf(h[6],h[7]));
        uint4 lv = make_uint4(pack_bf(l[0],l[1]), pack_bf(l[2],l[3]),
                              pack_bf(l[4],l[5]), pack_bf(l[6],l[7]));
        int off = k * 272 + n0 * 2;
        *(uint4*)(sbuf + BH_O + off) = hv;
        *(uint4*)(sbuf + BL_O + off) = lv;
    }
}

template<int MODE, int LSEL>
__global__ void __launch_bounds__(256, 1) mma_gemm(
    const float* __restrict__ Aparam, const float* __restrict__ Bmat,
    const float* __restrict__ bias, const float* __restrict__ extra,
    float* __restrict__ Cparam, int N, int K, int ldb)
{
    extern __shared__ char smem[];
    const uint32_t sb = smem_u32(smem);
    const int tid = threadIdx.x;
    const int wid = tid >> 5;
    const int lane = tid & 31;
    const int warp_m = wid & 3;
    const int warp_n = wid >> 2;

    const float* A = (MODE == 0) ? Aparam : (MODE == 1 ? (LSEL ? g_x1 : g_x0) : g_pool);
    const int lda = K;

    const int bm = blockIdx.y * 128;
    const int bn = blockIdx.x * 128;
    const int NCH = (K + 31) >> 5;

    // ldmatrix lane-address components
    const int sub = lane >> 3;
    const int l7 = lane & 7;
    const uint32_t a_off = (uint32_t)((warp_m * 32 + (sub & 1) * 8 + l7) * 80
                                      + ((sub >> 1) * 8) * 2);
    const uint32_t b_off = (uint32_t)(((sub & 1) * 8 + l7) * 272
                                      + (warp_n * 64 + (sub >> 1) * 8) * 2);

    float acc[2][8][4];
    #pragma unroll
    for (int mt = 0; mt < 2; mt++)
        #pragma unroll
        for (int nt = 0; nt < 8; nt++)
            #pragma unroll
            for (int q = 0; q < 4; q++) acc[mt][nt][q] = 0.f;

    float va[2][8], vb[2][8];
    load_A<MODE>(A, lda, K, bm, 0, tid, va);
    load_B<MODE>(Bmat, ldb, K, N, bn, 0, tid, vb);
    store_stage(smem, tid, va, vb);
    __syncthreads();

    for (int c = 0; c < NCH; c++) {
        if (c + 1 < NCH) {
            load_A<MODE>(A, lda, K, bm, (c + 1) << 5, tid, va);
            load_B<MODE>(Bmat, ldb, K, N, bn, (c + 1) << 5, tid, vb);
        }
        const uint32_t stg = sb + (uint32_t)((c & 1) * STG_SZ);
        #pragma unroll
        for (int ks = 0; ks < 2; ks++) {
            uint32_t ah[2][4], al[2][4], bh[8][2], bl[8][2];
            #pragma unroll
            for (int mt = 0; mt < 2; mt++) {
                uint32_t ad = stg + AH_O + a_off + mt * (16 * 80) + ks * 32;
                LDSM4(ah[mt], ad);
                LDSM4(al[mt], ad + (AL_O - AH_O));
            }
            #pragma unroll
            for (int p = 0; p < 4; p++) {
                uint32_t bd = stg + BH_O + b_off + p * 32 + ks * (16 * 272);
                uint32_t r[4];
                LDSM4T(r, bd);
                bh[2*p][0] = r[0]; bh[2*p][1] = r[1];
                bh[2*p+1][0] = r[2]; bh[2*p+1][1] = r[3];
                LDSM4T(r, bd + (BL_O - BH_O));
                bl[2*p][0] = r[0]; bl[2*p][1] = r[1];
                bl[2*p+1][0] = r[2]; bl[2*p+1][1] = r[3];
            }
            #pragma unroll
            for (int mt = 0; mt < 2; mt++)
                #pragma unroll
                for (int nt = 0; nt < 8; nt++) {
                    MMA16816(acc[mt][nt], ah[mt], bh[nt]);
                    MMA16816(acc[mt][nt], ah[mt], bl[nt]);
                    MMA16816(acc[mt][nt], al[mt], bh[nt]);
                }
        }
        __syncthreads();
        if (c + 1 < NCH) {
            store_stage(smem + ((c + 1) & 1) * STG_SZ, tid, va, vb);
            __syncthreads();
        }
    }

    // Epilogue. Thread t of each warp: rows g, g+8; cols q*2, q*2+1 per tile.
    const int g = lane >> 2;
    const int qc = (lane & 3) * 2;
    #pragma unroll
    for (int mt = 0; mt < 2; mt++) {
        const int m0 = bm + warp_m * 32 + mt * 16 + g;
        #pragma unroll
        for (int nt = 0; nt < 8; nt++) {
            const int n = bn + warp_n * 64 + nt * 8 + qc;
            const float* a = acc[mt][nt];
            if (MODE == 0) {
                float b0 = bias[n], b1 = bias[n + 1];
                int bb = m0 / T_, tt = m0 - bb * T_;
                float2 w0 = make_float2(tanhf(a[0] + b0), tanhf(a[1] + b1));
                *(float2*)(g_x0 + ((size_t)tt * B_ + bb) * H_ + n) = w0;
                int m1 = m0 + 8;
                int bb1 = m1 / T_, tt1 = m1 - bb1 * T_;
                float2 w1 = make_float2(tanhf(a[2] + b0), tanhf(a[3] + b1));
                *(float2*)(g_x0 + ((size_t)tt1 * B_ + bb1) * H_ + n) = w1;
            } else if (MODE == 1) {
                *(float2*)(g_U + (size_t)m0 * (3 * H_) + n) = make_float2(a[0], a[1]);
                *(float2*)(g_U + (size_t)(m0 + 8) * (3 * H_) + n) = make_float2(a[2], a[3]);
            } else {
                #pragma unroll
                for (int rr = 0; rr < 2; rr++) {
                    int m = m0 + rr * 8;
                    #pragma unroll
                    for (int cc = 0; cc < 2; cc++) {
                        int nn = n + cc;
                        if (nn < N) {
                            float s = sigmoidf_(a[rr * 2 + cc] + bias[nn]);
                            Cparam[(size_t)m * IND_ + nn] =
                                s * extra[(size_t)m * FEAT_ + IND_ + nn];
                        }
                    }
                }
            }
        }
    }
}

// ---------------------------------------------------------------------------
// SRU sequential scan (unchanged)
// ---------------------------------------------------------------------------
template<int L>
__global__ void sru_scan(const float* __restrict__ v, const float* __restrict__ bb)
{
    const float* xin  = (L == 0) ? g_x0 : g_x1;
    float*       xout = (L == 0) ? g_x1 : g_x0;
    int idx = blockIdx.x * blockDim.x + threadIdx.x;
    if (idx >= B_ * H_) return;
    int b = idx / H_;
    int h = idx % H_;
    float vf = v[h],  vr = v[H_ + h];
    float bf = bb[h], br = bb[H_ + h];
    float c = 0.f;
    const float* Ur = g_U + (size_t)b * 3 * H_ + h;
    const float* xr = xin + (size_t)b * H_ + h;
    float*       xo = xout + (size_t)b * H_ + h;
    #pragma unroll 4
    for (int t = 0; t < T_; t++) {
        float xt = Ur[0];
        float fp = Ur[H_];
        float rp = Ur[2 * H_];
        float xi = xr[0];
        float f  = sigmoidf_(fp + vf * c + bf);
        float cn = f * c + (1.f - f) * xt;
        float r  = sigmoidf_(rp + vr * c + br);
        xo[0] = r * cn + (1.f - r) * xi;
        c = cn;
        Ur += B_ * 3 * H_;
        xr += B_ * H_;
        xo += B_ * H_;
    }
}

// ---------------------------------------------------------------------------
// Conv2d 6x6 (out_ch=9), pad (3,2)x(3,2), +bias, tanh (unchanged)
// ---------------------------------------------------------------------------
__global__ void conv_kernel(const float* __restrict__ ck, const float* __restrict__ cb)
{
    __shared__ float sk[KN_ * 36];
    for (int i = threadIdx.x; i < KN_ * 36; i += blockDim.x) sk[i] = ck[i];
    __syncthreads();
    int idx = blockIdx.x * blockDim.x + threadIdx.x;
    const int total = B_ * KN_ * T_ * H_;
    if (idx >= total) return;
    int h  = idx & (H_ - 1);
    int t  = (idx / H_) % T_;
    int kn = (idx / (H_ * T_)) % KN_;
    int b  = idx / (H_ * T_ * KN_);
    const float* w = &sk[kn * 36];
    float s = 0.f;
    int ilo = (t >= 3) ? 0 : (3 - t);
    int ihi = min(6, T_ + 3 - t);
    int jlo = (h >= 3) ? 0 : (3 - h);
    int jhi = min(6, H_ + 3 - h);
    for (int i = ilo; i < ihi; i++) {
        const float* xr = &g_x0[((size_t)(t + i - 3) * B_ + b) * H_ + (h - 3)];
        const float* wr = &w[i * 6];
        for (int j = jlo; j < jhi; j++) s += xr[j] * wr[j];
    }
    g_conv[idx] = tanhf(s + cb[kn]);
}

// ---------------------------------------------------------------------------
// MaxPool 3x3 s1 p1 + layout permute (unchanged)
// ---------------------------------------------------------------------------
__global__ void pool_kernel()
{
    int idx = blockIdx.x * blockDim.x + threadIdx.x;
    const int total = B_ * T_ * KN_ * H_;
    if (idx >= total) return;
    int h  = idx & (H_ - 1);
    int kn = (idx / H_) % KN_;
    int t  = (idx / (H_ * KN_)) % T_;
    int b  = idx / (H_ * KN_ * T_);
    const float* base = &g_conv[(size_t)(b * KN_ + kn) * T_ * H_];
    float m = -1e30f;
    int t0 = max(t - 1, 0), t1 = min(t + 1, T_ - 1);
    int h0 = max(h - 1, 0), h1 = min(h + 1, H_ - 1);
    for (int tt = t0; tt <= t1; tt++)
        for (int hh = h0; hh <= h1; hh++)
            m = fmaxf(m, base[(size_t)tt * H_ + hh]);
    g_pool[idx] = m;
}

// ---------------------------------------------------------------------------
extern "C" void kernel_launch(void* const* d_in, const int* in_sizes, int n_in,
                              void* d_out, int out_size)
{
    (void)in_sizes; (void)n_in; (void)out_size;
    const float* inputs = (const float*)d_in[0];
    const float* W_in   = (const float*)d_in[1];
    const float* b_in   = (const float*)d_in[2];
    const float* W_rnn  = (const float*)d_in[3];
    const float* v_rnn  = (const float*)d_in[4];
    const float* b_rnn  = (const float*)d_in[5];
    const float* conv_k = (const float*)d_in[6];
    const float* conv_b = (const float*)d_in[7];
    const float* W_out  = (const float*)d_in[8];
    const float* b_out  = (const float*)d_in[9];
    float* out = (float*)d_out;

    cudaFuncSetAttribute(mma_gemm<0,0>, cudaFuncAttributeMaxDynamicSharedMemorySize, MMA_SMEM);
    cudaFuncSetAttribute(mma_gemm<1,0>, cudaFuncAttributeMaxDynamicSharedMemorySize, MMA_SMEM);
    cudaFuncSetAttribute(mma_gemm<1,1>, cudaFuncAttributeMaxDynamicSharedMemorySize, MMA_SMEM);
    cudaFuncSetAttribute(mma_gemm<2,0>, cudaFuncAttributeMaxDynamicSharedMemorySize, MMA_SMEM);

    // Input layer: tanh(inputs @ W_in + b_in) -> g_x0 (time-major)
    mma_gemm<0,0><<<dim3(4, 125), 256, MMA_SMEM>>>(inputs, W_in, b_in, nullptr, nullptr,
                                                   H_, FEAT_, H_);
    // SRU layer 0
    mma_gemm<1,0><<<dim3(12, 125), 256, MMA_SMEM>>>(nullptr, W_rnn, nullptr, nullptr, nullptr,
                                                    3 * H_, H_, 3 * H_);
    sru_scan<0><<<64, 128>>>(v_rnn, b_rnn);
    // SRU layer 1
    mma_gemm<1,1><<<dim3(12, 125), 256, MMA_SMEM>>>(nullptr, W_rnn + (size_t)H_ * 3 * H_,
                                                    nullptr, nullptr, nullptr,
                                                    3 * H_, H_, 3 * H_);
    sru_scan<1><<<64, 128>>>(v_rnn + 2 * H_, b_rnn + 2 * H_);
    // Conv + tanh
    conv_kernel<<<(B_ * KN_ * T_ * H_ + 255) / 256, 256>>>(conv_k, conv_b);
    // MaxPool + layout permute
    pool_kernel<<<(B_ * T_ * KN_ * H_ + 255) / 256, 256>>>();
    // Output GEMM (center 257 cols) + sigmoid * inputs
    mma_gemm<2,0><<<dim3(3, 125), 256, MMA_SMEM>>>(nullptr, W_out, b_out + IND_, inputs, out,
                                                   IND_, KN_ * H_, FEAT_);
}

// round 4
// speedup vs baseline: 2.8350x; 1.9081x over previous
#include <cuda_runtime.h>
#include <cuda_bf16.h>
#include <math.h>
#include <stdint.h>

// Problem constants
#define B_ 16
#define T_ 1000
#define FEAT_ 771
#define H_ 512
#define KN_ 9
#define IND_ 257
#define M_ (B_ * T_)          // 16000

// Scratch (device globals; allocation is banned)
__device__ float g_x0[(size_t)T_ * B_ * H_];        // (T,B,H)
__device__ float g_x1[(size_t)T_ * B_ * H_];
__device__ float g_U[(size_t)M_ * 3 * H_];          // rows m = t*B+b
__device__ float g_pool[(size_t)M_ * KN_ * H_];     // ((b,t),kn,h)
__device__ float g_wc[KN_ * H_];                    // W_out column 513 gathered

__device__ __forceinline__ float sigmoidf_(float x) {
    return 1.0f / (1.0f + __expf(-x));
}
__device__ __forceinline__ float tanh_fast(float x) {
    float e = __expf(2.0f * x);
    return 1.0f - 2.0f / (e + 1.0f);
}

__device__ __forceinline__ uint32_t smem_u32(const void* p) {
    uint32_t a;
    asm("{ .reg .u64 t; cvta.to.shared.u64 t, %1; cvt.u32.u64 %0, t; }"
        : "=r"(a) : "l"(p));
    return a;
}

// cp.async (sm_80 baseline)
#define CP4(dst, src) \
    asm volatile("cp.async.ca.shared.global [%0], [%1], 4;" :: "r"(dst), "l"(src))
#define CP_COMMIT asm volatile("cp.async.commit_group;" ::: "memory")
#define CP_WAIT(n) asm volatile("cp.async.wait_group %0;" :: "n"(n) : "memory")

// ===========================================================================
// Warp-MMA bf16 helpers
// ===========================================================================
#define LDSM4(r, addr) \
    asm volatile("ldmatrix.sync.aligned.m8n8.x4.shared.b16 {%0,%1,%2,%3}, [%4];" \
        : "=r"((r)[0]), "=r"((r)[1]), "=r"((r)[2]), "=r"((r)[3]) : "r"(addr))
#define LDSM4T(r, addr) \
    asm volatile("ldmatrix.sync.aligned.m8n8.x4.trans.shared.b16 {%0,%1,%2,%3}, [%4];" \
        : "=r"((r)[0]), "=r"((r)[1]), "=r"((r)[2]), "=r"((r)[3]) : "r"(addr))
#define MMA16816(c, a, b) \
    asm volatile("mma.sync.aligned.m16n8k16.row.col.f32.bf16.bf16.f32 " \
        "{%0,%1,%2,%3}, {%4,%5,%6,%7}, {%8,%9}, {%0,%1,%2,%3};" \
        : "+f"((c)[0]), "+f"((c)[1]), "+f"((c)[2]), "+f"((c)[3]) \
        : "r"((a)[0]), "r"((a)[1]), "r"((a)[2]), "r"((a)[3]), \
          "r"((b)[0]), "r"((b)[1]))

__device__ __forceinline__ uint32_t pack_bf(float lo, float hi) {
    uint32_t r;
    asm("cvt.rn.bf16x2.f32 %0, %1, %2;" : "=r"(r) : "f"(hi), "f"(lo));
    return r;
}
__device__ __forceinline__ void split_hl(float x, float& h, float& l) {
    h = __bfloat162float(__float2bfloat16_rn(x));
    l = x - h;
}

// Smem layout (per stage): Ah[128][40h] 80B rows, Al, Bh[32][136h] 272B rows, Bl
#define AH_O 0
#define AL_O 10240
#define BH_O 20480
#define BL_O 29184
#define STG_SZ 37888
#define MMA_SMEM (2 * STG_SZ)   // 75776 bytes

template<int MODE>
__device__ __forceinline__ void load_A(const float* __restrict__ A, int lda, int K,
                                       int bm, int k0, int tid, float v[2][8]) {
    #pragma unroll
    for (int it = 0; it < 2; it++) {
        int slot = tid + it * 256;
        int m = slot >> 2;
        int kg = (slot & 3) * 8;
        const float* src = A + (size_t)(bm + m) * lda + k0 + kg;
        if (MODE == 0) {
            #pragma unroll
            for (int j = 0; j < 8; j++)
                v[it][j] = (k0 + kg + j < K) ? src[j] : 0.f;
        } else {
            float4 p0 = *(const float4*)(src);
            float4 p1 = *(const float4*)(src + 4);
            v[it][0] = p0.x; v[it][1] = p0.y; v[it][2] = p0.z; v[it][3] = p0.w;
            v[it][4] = p1.x; v[it][5] = p1.y; v[it][6] = p1.z; v[it][7] = p1.w;
        }
    }
}

template<int MODE>
__device__ __forceinline__ void load_B(const float* __restrict__ Bm, int ldb, int K,
                                       int N, int bn, int k0, int tid, float v[2][8]) {
    #pragma unroll
    for (int it = 0; it < 2; it++) {
        int slot = tid + it * 256;
        int k = slot >> 4;
        int n0 = (slot & 15) * 8;
        int kg = k0 + k;
        if (MODE == 2) {
            int kn = kg >> 9, hh = kg & 511;
            const float* src = Bm + (size_t)(hh * KN_ + kn) * ldb + IND_ + bn + n0;
            #pragma unroll
            for (int j = 0; j < 8; j++)
                v[it][j] = (bn + n0 + j < N) ? src[j] : 0.f;
        } else {
            const float* src = Bm + (size_t)kg * ldb + bn + n0;
            if (kg < K) {
                float4 p0 = *(const float4*)(src);
                float4 p1 = *(const float4*)(src + 4);
                v[it][0] = p0.x; v[it][1] = p0.y; v[it][2] = p0.z; v[it][3] = p0.w;
                v[it][4] = p1.x; v[it][5] = p1.y; v[it][6] = p1.z; v[it][7] = p1.w;
            } else {
                #pragma unroll
                for (int j = 0; j < 8; j++) v[it][j] = 0.f;
            }
        }
    }
}

__device__ __forceinline__ void store_stage(char* sbuf, int tid,
                                            float va[2][8], float vb[2][8]) {
    #pragma unroll
    for (int it = 0; it < 2; it++) {
        int slot = tid + it * 256;
        int m = slot >> 2;
        int kg = (slot & 3) * 8;
        float h[8], l[8];
        #pragma unroll
        for (int j = 0; j < 8; j++) split_hl(va[it][j], h[j], l[j]);
        uint4 hv = make_uint4(pack_bf(h[0],h[1]), pack_bf(h[2],h[3]),
                              pack_bf(h[4],h[5]), pack_bf(h[6],h[7]));
        uint4 lv = make_uint4(pack_bf(l[0],l[1]), pack_bf(l[2],l[3]),
                              pack_bf(l[4],l[5]), pack_bf(l[6],l[7]));
        int off = m * 80 + kg * 2;
        *(uint4*)(sbuf + AH_O + off) = hv;
        *(uint4*)(sbuf + AL_O + off) = lv;
    }
    #pragma unroll
    for (int it = 0; it < 2; it++) {
        int slot = tid + it * 256;
        int k = slot >> 4;
        int n0 = (slot & 15) * 8;
        float h[8], l[8];
        #pragma unroll
        for (int j = 0; j < 8; j++) split_hl(vb[it][j], h[j], l[j]);
        uint4 hv = make_uint4(pack_bf(h[0],h[1]), pack_bf(h[2],h[3]),
                              pack_bf(h[4],h[5]), pack_bf(h[6],h[7]));
        uint4 lv = make_uint4(pack_bf(l[0],l[1]), pack_bf(l[2],l[3]),
                              pack_bf(l[4],l[5]), pack_bf(l[6],l[7]));
        int off = k * 272 + n0 * 2;
        *(uint4*)(sbuf + BH_O + off) = hv;
        *(uint4*)(sbuf + BL_O + off) = lv;
    }
}

template<int MODE, int LSEL>
__global__ void __launch_bounds__(256, 1) mma_gemm(
    const float* __restrict__ Aparam, const float* __restrict__ Bmat,
    const float* __restrict__ bias, const float* __restrict__ extra,
    float* __restrict__ Cparam, int N, int K, int ldb)
{
    extern __shared__ char smem[];
    const uint32_t sb = smem_u32(smem);
    const int tid = threadIdx.x;
    const int wid = tid >> 5;
    const int lane = tid & 31;
    const int warp_m = wid & 3;
    const int warp_n = wid >> 2;

    const float* A = (MODE == 0) ? Aparam : (MODE == 1 ? (LSEL ? g_x1 : g_x0) : g_pool);
    const int lda = K;

    const int bm = blockIdx.y * 128;
    const int bn = blockIdx.x * 128;
    const int NCH = (K + 31) >> 5;

    const int sub = lane >> 3;
    const int l7 = lane & 7;
    const uint32_t a_off = (uint32_t)((warp_m * 32 + (sub & 1) * 8 + l7) * 80
                                      + ((sub >> 1) * 8) * 2);
    const uint32_t b_off = (uint32_t)(((sub & 1) * 8 + l7) * 272
                                      + (warp_n * 64 + (sub >> 1) * 8) * 2);

    float acc[2][8][4];
    #pragma unroll
    for (int mt = 0; mt < 2; mt++)
        #pragma unroll
        for (int nt = 0; nt < 8; nt++)
            #pragma unroll
            for (int q = 0; q < 4; q++) acc[mt][nt][q] = 0.f;

    float va[2][8], vb[2][8];
    load_A<MODE>(A, lda, K, bm, 0, tid, va);
    load_B<MODE>(Bmat, ldb, K, N, bn, 0, tid, vb);
    store_stage(smem, tid, va, vb);
    __syncthreads();

    for (int c = 0; c < NCH; c++) {
        if (c + 1 < NCH) {
            load_A<MODE>(A, lda, K, bm, (c + 1) << 5, tid, va);
            load_B<MODE>(Bmat, ldb, K, N, bn, (c + 1) << 5, tid, vb);
        }
        const uint32_t stg = sb + (uint32_t)((c & 1) * STG_SZ);
        #pragma unroll
        for (int ks = 0; ks < 2; ks++) {
            uint32_t ah[2][4], al[2][4], bh[8][2], bl[8][2];
            #pragma unroll
            for (int mt = 0; mt < 2; mt++) {
                uint32_t ad = stg + AH_O + a_off + mt * (16 * 80) + ks * 32;
                LDSM4(ah[mt], ad);
                LDSM4(al[mt], ad + (AL_O - AH_O));
            }
            #pragma unroll
            for (int p = 0; p < 4; p++) {
                uint32_t bd = stg + BH_O + b_off + p * 32 + ks * (16 * 272);
                uint32_t r[4];
                LDSM4T(r, bd);
                bh[2*p][0] = r[0]; bh[2*p][1] = r[1];
                bh[2*p+1][0] = r[2]; bh[2*p+1][1] = r[3];
                LDSM4T(r, bd + (BL_O - BH_O));
                bl[2*p][0] = r[0]; bl[2*p][1] = r[1];
                bl[2*p+1][0] = r[2]; bl[2*p+1][1] = r[3];
            }
            #pragma unroll
            for (int mt = 0; mt < 2; mt++)
                #pragma unroll
                for (int nt = 0; nt < 8; nt++) {
                    MMA16816(acc[mt][nt], ah[mt], bh[nt]);
                    MMA16816(acc[mt][nt], ah[mt], bl[nt]);
                    MMA16816(acc[mt][nt], al[mt], bh[nt]);
                }
        }
        __syncthreads();
        if (c + 1 < NCH) {
            store_stage(smem + ((c + 1) & 1) * STG_SZ, tid, va, vb);
            __syncthreads();
        }
    }

    const int g = lane >> 2;
    const int qc = (lane & 3) * 2;
    #pragma unroll
    for (int mt = 0; mt < 2; mt++) {
        const int m0 = bm + warp_m * 32 + mt * 16 + g;
        #pragma unroll
        for (int nt = 0; nt < 8; nt++) {
            const int n = bn + warp_n * 64 + nt * 8 + qc;
            const float* a = acc[mt][nt];
            if (MODE == 0) {
                float b0 = bias[n], b1 = bias[n + 1];
                int bb = m0 / T_, tt = m0 - bb * T_;
                float2 w0 = make_float2(tanh_fast(a[0] + b0), tanh_fast(a[1] + b1));
                *(float2*)(g_x0 + ((size_t)tt * B_ + bb) * H_ + n) = w0;
                int m1 = m0 + 8;
                int bb1 = m1 / T_, tt1 = m1 - bb1 * T_;
                float2 w1 = make_float2(tanh_fast(a[2] + b0), tanh_fast(a[3] + b1));
                *(float2*)(g_x0 + ((size_t)tt1 * B_ + bb1) * H_ + n) = w1;
            } else if (MODE == 1) {
                *(float2*)(g_U + (size_t)m0 * (3 * H_) + n) = make_float2(a[0], a[1]);
                *(float2*)(g_U + (size_t)(m0 + 8) * (3 * H_) + n) = make_float2(a[2], a[3]);
            } else {
                #pragma unroll
                for (int rr = 0; rr < 2; rr++) {
                    int m = m0 + rr * 8;
                    #pragma unroll
                    for (int cc = 0; cc < 2; cc++) {
                        int nn = n + cc;
                        float s = sigmoidf_(a[rr * 2 + cc] + bias[nn]);
                        Cparam[(size_t)m * IND_ + nn] =
                            s * extra[(size_t)m * FEAT_ + IND_ + nn];
                    }
                }
            }
        }
    }
}

// ---------------------------------------------------------------------------
// SRU sequential scan with cp.async depth-15 prefetch ring (16 slots).
// grid (4, 16): h-chunk, b. 128 threads; thread owns one (b,h) chain.
// ---------------------------------------------------------------------------
template<int L>
__global__ void __launch_bounds__(128) sru_scan(const float* __restrict__ v,
                                                const float* __restrict__ bb)
{
    __shared__ float s[4][16][128];
    const float* xin  = (L == 0) ? g_x0 : g_x1;
    float*       xout = (L == 0) ? g_x1 : g_x0;
    const int tid = threadIdx.x;
    const int b = blockIdx.y;
    const int h = blockIdx.x * 128 + tid;

    const float vf = v[h],  vr = v[H_ + h];
    const float bf = bb[h], br = bb[H_ + h];

    auto issue = [&](int u) {
        int slot = u & 15;
        const float* Ub = g_U + ((size_t)u * B_ + b) * (3 * H_) + h;
        const float* Xb = xin + ((size_t)u * B_ + b) * H_ + h;
        CP4(smem_u32(&s[0][slot][tid]), Ub);
        CP4(smem_u32(&s[1][slot][tid]), Ub + H_);
        CP4(smem_u32(&s[2][slot][tid]), Ub + 2 * H_);
        CP4(smem_u32(&s[3][slot][tid]), Xb);
        CP_COMMIT;
    };
    #pragma unroll
    for (int u = 0; u < 15; u++) issue(u);

    float c = 0.f;
    float* xo = xout + (size_t)b * H_ + h;
    int t = 0;
    for (; t < T_ - 15; t++) {
        CP_WAIT(14);
        int slot = t & 15;
        float xt = s[0][slot][tid], fp = s[1][slot][tid];
        float rp = s[2][slot][tid], xi = s[3][slot][tid];
        float f  = sigmoidf_(fp + vf * c + bf);
        float cn = f * c + (1.f - f) * xt;
        float r  = sigmoidf_(rp + vr * c + br);
        xo[(size_t)t * B_ * H_] = r * cn + (1.f - r) * xi;
        c = cn;
        issue(t + 15);
    }
    CP_WAIT(0);
    for (; t < T_; t++) {
        int slot = t & 15;
        float xt = s[0][slot][tid], fp = s[1][slot][tid];
        float rp = s[2][slot][tid], xi = s[3][slot][tid];
        float f  = sigmoidf_(fp + vf * c + bf);
        float cn = f * c + (1.f - f) * xt;
        float r  = sigmoidf_(rp + vr * c + br);
        xo[(size_t)t * B_ * H_] = r * cn + (1.f - r) * xi;
        c = cn;
    }
}

// ---------------------------------------------------------------------------
// Fused Conv2d 6x6 (+bias, tanh) + MaxPool 3x3 s1 p1 + layout permute.
// Pool tile 16(t) x 64(h) per block per kn; conv tile 18x66 in smem;
// x tile 23x71 in smem (zero-padded). Writes g_pool ((b,t),kn,h) directly.
// Invalid conv positions (outside [0,T)x[0,H)) = -1e30 so pool ignores them.
// ---------------------------------------------------------------------------
__global__ void __launch_bounds__(256) convpool_kernel(const float* __restrict__ ck,
                                                       const float* __restrict__ cb)
{
    __shared__ float xs[23][73];
    __shared__ float cs[18][68];
    __shared__ float sk[KN_ * 36];
    const int tid = threadIdx.x;
    const int h0 = blockIdx.x * 64;
    const int t0 = blockIdx.y * 16;
    const int b  = blockIdx.z;

    for (int i = tid; i < KN_ * 36; i += 256) sk[i] = ck[i];

    for (int idx = tid; idx < 23 * 73; idx += 256) {
        int row = idx / 73, col = idx % 73;
        if (col < 71) {
            int gt = t0 - 4 + row, gh = h0 - 4 + col;
            float val = 0.f;
            if (gt >= 0 && gt < T_ && gh >= 0 && gh < H_)
                val = g_x0[((size_t)gt * B_ + b) * H_ + gh];
            xs[row][col] = val;
        }
    }
    __syncthreads();

    for (int kn = 0; kn < KN_; kn++) {
        const float cbias = cb[kn];
        const float* w = &sk[kn * 36];
        // conv: 18 rows x 17 strips of 4 cols = 306 tasks
        for (int sidx = tid; sidx < 306; sidx += 256) {
            int ci = sidx % 18;
            int cj0 = (sidx / 18) * 4;
            int gt = t0 - 1 + ci;
            float a0 = 0.f, a1 = 0.f, a2 = 0.f, a3 = 0.f;
            #pragma unroll
            for (int i = 0; i < 6; i++) {
                float x9[9];
                #pragma unroll
                for (int j = 0; j < 9; j++) x9[j] = xs[ci + i][cj0 + j];
                #pragma unroll
                for (int j = 0; j < 6; j++) {
                    float wv = w[i * 6 + j];
                    a0 = fmaf(x9[j],     wv, a0);
                    a1 = fmaf(x9[j + 1], wv, a1);
                    a2 = fmaf(x9[j + 2], wv, a2);
                    a3 = fmaf(x9[j + 3], wv, a3);
                }
            }
            bool tv = (gt >= 0 && gt < T_);
            float av[4] = {a0, a1, a2, a3};
            #pragma unroll
            for (int q = 0; q < 4; q++) {
                int cj = cj0 + q;
                if (cj < 66) {
                    int gh = h0 - 1 + cj;
                    cs[ci][cj] = (tv && gh >= 0 && gh < H_)
                               ? tanh_fast(av[q] + cbias) : -1e30f;
                }
            }
        }
        __syncthreads();
        // pool: thread -> 1x4 strip
        {
            int ti = tid >> 4;
            int hj0 = (tid & 15) * 4;
            int gt = t0 + ti;
            if (gt < T_) {
                float o0 = -1e30f, o1 = -1e30f, o2 = -1e30f, o3 = -1e30f;
                #pragma unroll
                for (int r = 0; r < 3; r++) {
                    float c6[6];
                    #pragma unroll
                    for (int j = 0; j < 6; j++) c6[j] = cs[ti + r][hj0 + j];
                    o0 = fmaxf(o0, fmaxf(c6[0], fmaxf(c6[1], c6[2])));
                    o1 = fmaxf(o1, fmaxf(c6[1], fmaxf(c6[2], c6[3])));
                    o2 = fmaxf(o2, fmaxf(c6[2], fmaxf(c6[3], c6[4])));
                    o3 = fmaxf(o3, fmaxf(c6[3], fmaxf(c6[4], c6[5])));
                }
                float4 o = make_float4(o0, o1, o2, o3);
                *(float4*)&g_pool[(((size_t)b * T_ + gt) * KN_ + kn) * H_ + h0 + hj0] = o;
            }
        }
        __syncthreads();
    }
}

// ---------------------------------------------------------------------------
// Gather W_out column (IND_+256) into g_wc (k = kn*512 + h -> row h*9+kn)
// ---------------------------------------------------------------------------
__global__ void prep_wc(const float* __restrict__ W_out)
{
    int idx = blockIdx.x * 256 + threadIdx.x;
    if (idx < KN_ * H_) {
        int kn = idx >> 9, h = idx & 511;
        g_wc[idx] = W_out[(size_t)(h * KN_ + kn) * FEAT_ + IND_ + 256];
    }
}

// ---------------------------------------------------------------------------
// GEMV for output column 256: one warp per row m, K=4608.
// ---------------------------------------------------------------------------
__global__ void __launch_bounds__(256) gemv_kernel(const float* __restrict__ inputs,
                                                   const float* __restrict__ b_out,
                                                   float* __restrict__ out)
{
    __shared__ float swc[KN_ * H_];
    const int tid = threadIdx.x, wid = tid >> 5, lane = tid & 31;
    float4* s4 = (float4*)swc;
    for (int i = tid; i < (KN_ * H_) / 4; i += 256)
        s4[i] = ((const float4*)g_wc)[i];
    __syncthreads();
    const int m = blockIdx.x * 8 + wid;
    const float4* pr = (const float4*)(g_pool + (size_t)m * (KN_ * H_));
    float s = 0.f;
    for (int i = lane; i < (KN_ * H_) / 4; i += 32) {
        float4 a = pr[i], w = s4[i];
        s += a.x * w.x + a.y * w.y + a.z * w.z + a.w * w.w;
    }
    #pragma unroll
    for (int o = 16; o; o >>= 1) s += __shfl_xor_sync(0xffffffffu, s, o);
    if (lane == 0) {
        float sg = sigmoidf_(s + b_out[IND_ + 256]);
        out[(size_t)m * IND_ + 256] = sg * inputs[(size_t)m * FEAT_ + IND_ + 256];
    }
}

// ---------------------------------------------------------------------------
extern "C" void kernel_launch(void* const* d_in, const int* in_sizes, int n_in,
                              void* d_out, int out_size)
{
    (void)in_sizes; (void)n_in; (void)out_size;
    const float* inputs = (const float*)d_in[0];
    const float* W_in   = (const float*)d_in[1];
    const float* b_in   = (const float*)d_in[2];
    const float* W_rnn  = (const float*)d_in[3];
    const float* v_rnn  = (const float*)d_in[4];
    const float* b_rnn  = (const float*)d_in[5];
    const float* conv_k = (const float*)d_in[6];
    const float* conv_b = (const float*)d_in[7];
    const float* W_out  = (const float*)d_in[8];
    const float* b_out  = (const float*)d_in[9];
    float* out = (float*)d_out;

    cudaFuncSetAttribute(mma_gemm<0,0>, cudaFuncAttributeMaxDynamicSharedMemorySize, MMA_SMEM);
    cudaFuncSetAttribute(mma_gemm<1,0>, cudaFuncAttributeMaxDynamicSharedMemorySize, MMA_SMEM);
    cudaFuncSetAttribute(mma_gemm<1,1>, cudaFuncAttributeMaxDynamicSharedMemorySize, MMA_SMEM);
    cudaFuncSetAttribute(mma_gemm<2,0>, cudaFuncAttributeMaxDynamicSharedMemorySize, MMA_SMEM);

    // Independent: gather W_out column for the GEMV
    prep_wc<<<(KN_ * H_ + 255) / 256, 256>>>(W_out);

    // Input layer: tanh(inputs @ W_in + b_in) -> g_x0 (time-major)
    mma_gemm<0,0><<<dim3(4, 125), 256, MMA_SMEM>>>(inputs, W_in, b_in, nullptr, nullptr,
                                                   H_, FEAT_, H_);
    // SRU layer 0
    mma_gemm<1,0><<<dim3(12, 125), 256, MMA_SMEM>>>(nullptr, W_rnn, nullptr, nullptr, nullptr,
                                                    3 * H_, H_, 3 * H_);
    sru_scan<0><<<dim3(4, 16), 128>>>(v_rnn, b_rnn);
    // SRU layer 1
    mma_gemm<1,1><<<dim3(12, 125), 256, MMA_SMEM>>>(nullptr, W_rnn + (size_t)H_ * 3 * H_,
                                                    nullptr, nullptr, nullptr,
                                                    3 * H_, H_, 3 * H_);
    sru_scan<1><<<dim3(4, 16), 128>>>(v_rnn + 2 * H_, b_rnn + 2 * H_);
    // Fused conv + tanh + maxpool -> g_pool
    convpool_kernel<<<dim3(8, 63, 16), 256>>>(conv_k, conv_b);
    // Output GEMM (cols 0..255) + sigmoid * inputs
    mma_gemm<2,0><<<dim3(2, 125), 256, MMA_SMEM>>>(nullptr, W_out, b_out + IND_, inputs, out,
                                                   256, KN_ * H_, FEAT_);
    // Output column 256 via GEMV
    gemv_kernel<<<M_ / 8, 256>>>(inputs, b_out, out);
}

// round 5
// speedup vs baseline: 3.0542x; 1.0773x over previous
#include <cuda_runtime.h>
#include <cuda_bf16.h>
#include <math.h>
#include <stdint.h>

// Problem constants
#define B_ 16
#define T_ 1000
#define FEAT_ 771
#define H_ 512
#define KN_ 9
#define IND_ 257
#define M_ (B_ * T_)          // 16000
#define KPAD_ 800             // FEAT_ padded to multiple of 32

typedef unsigned short u16;

// fp32 scratch
__device__ float g_x0[(size_t)T_ * B_ * H_];        // (T,B,H)
__device__ float g_x1[(size_t)T_ * B_ * H_];
__device__ float g_U[(size_t)M_ * 3 * H_];          // rows m = t*B+b
__device__ float g_wc[KN_ * H_];                    // W_out col 513 gathered

// bf16 hi/lo operand scratch
__device__ u16 g_ih[(size_t)M_ * KPAD_];            // inputs padded
__device__ u16 g_il[(size_t)M_ * KPAD_];
__device__ u16 g_w0h[KPAD_ * H_];                   // W_in padded
__device__ u16 g_w0l[KPAD_ * H_];
__device__ u16 g_w1h[2 * H_ * 3 * H_];              // W_rnn
__device__ u16 g_w1l[2 * H_ * 3 * H_];
__device__ u16 g_w3h[(KN_ * H_) * 256];             // W_out remapped, cols 257..512
__device__ u16 g_w3l[(KN_ * H_) * 256];
__device__ u16 g_x0h[(size_t)T_ * B_ * H_];
__device__ u16 g_x0l[(size_t)T_ * B_ * H_];
__device__ u16 g_x1h[(size_t)T_ * B_ * H_];
__device__ u16 g_x1l[(size_t)T_ * B_ * H_];
__device__ u16 g_ph[(size_t)M_ * KN_ * H_];         // pool ((b,t),kn,h)
__device__ u16 g_pl[(size_t)M_ * KN_ * H_];

__device__ __forceinline__ float sigmoidf_(float x) {
    return 1.0f / (1.0f + __expf(-x));
}
__device__ __forceinline__ float tanh_fast(float x) {
    float e = __expf(2.0f * x);
    return 1.0f - 2.0f / (e + 1.0f);
}
__device__ __forceinline__ uint32_t smem_u32(const void* p) {
    uint32_t a;
    asm("{ .reg .u64 t; cvta.to.shared.u64 t, %1; cvt.u32.u64 %0, t; }"
        : "=r"(a) : "l"(p));
    return a;
}
__device__ __forceinline__ u16 bf_hi(float x) {
    return __bfloat16_as_ushort(__float2bfloat16_rn(x));
}
__device__ __forceinline__ float bf_hif(float x) {
    return __bfloat162float(__float2bfloat16_rn(x));
}
__device__ __forceinline__ float bf2f(u16 u) {
    return __bfloat162float(__ushort_as_bfloat16(u));
}

// cp.async
#define CP4(dst, src) \
    asm volatile("cp.async.ca.shared.global [%0], [%1], 4;" :: "r"(dst), "l"(src))
#define CP16(dst, src) \
    asm volatile("cp.async.cg.shared.global [%0], [%1], 16;" :: "r"(dst), "l"(src))
#define CP_COMMIT asm volatile("cp.async.commit_group;" ::: "memory")
#define CP_WAIT(n) asm volatile("cp.async.wait_group %0;" :: "n"(n) : "memory")

// MMA helpers
#define LDSM4(r, addr) \
    asm volatile("ldmatrix.sync.aligned.m8n8.x4.shared.b16 {%0,%1,%2,%3}, [%4];" \
        : "=r"((r)[0]), "=r"((r)[1]), "=r"((r)[2]), "=r"((r)[3]) : "r"(addr))
#define LDSM4T(r, addr) \
    asm volatile("ldmatrix.sync.aligned.m8n8.x4.trans.shared.b16 {%0,%1,%2,%3}, [%4];" \
        : "=r"((r)[0]), "=r"((r)[1]), "=r"((r)[2]), "=r"((r)[3]) : "r"(addr))
#define MMA16816(c, a, b) \
    asm volatile("mma.sync.aligned.m16n8k16.row.col.f32.bf16.bf16.f32 " \
        "{%0,%1,%2,%3}, {%4,%5,%6,%7}, {%8,%9}, {%0,%1,%2,%3};" \
        : "+f"((c)[0]), "+f"((c)[1]), "+f"((c)[2]), "+f"((c)[3]) \
        : "r"((a)[0]), "r"((a)[1]), "r"((a)[2]), "r"((a)[3]), \
          "r"((b)[0]), "r"((b)[1]))

__device__ __forceinline__ uint32_t pack_bf(float lo, float hi) {
    uint32_t r;
    asm("cvt.rn.bf16x2.f32 %0, %1, %2;" : "=r"(r) : "f"(hi), "f"(lo));
    return r;
}

// Smem stage layout: Ah[128][40h] 80B rows, Al, Bh[32][136h] 272B rows, Bl
#define AH_O 0
#define AL_O 10240
#define BH_O 20480
#define BL_O 29184
#define STG_SZ 37888
#define GEMM_SMEM (4 * STG_SZ)   // 151552 bytes, 4-stage ring

// ===========================================================================
// cp.async-pipelined bf16 split GEMM. 128x128 CTA tile, 256 thr, BK=32,
// 4-stage ring, always-commit (wait_group 2 => stage c complete).
// D = Ah*Bh + Ah*Bl + Al*Bh in fp32 accumulators.
// MODE 0: A=g_ih/il [M,800], B=g_w0 [800,512] -> g_x0 tanh (+bf16 hi/lo)
// MODE 1: A=g_x{0,1}h/l [M,512], B=g_w1[l] [512,1536] -> g_U fp32
// MODE 2: A=g_ph/pl [M,4608], B=g_w3 [4608,256] -> out sigmoid*inputs
// ===========================================================================
template<int MODE, int LSEL>
__global__ void __launch_bounds__(256, 1) mma_gemm(
    const float* __restrict__ bias, const float* __restrict__ extra,
    float* __restrict__ Cparam, int N, int K, int lda, int ldbn)
{
    extern __shared__ char smem[];
    const uint32_t sb = smem_u32(smem);
    const int tid = threadIdx.x;
    const int wid = tid >> 5;
    const int lane = tid & 31;
    const int warp_m = wid & 3;
    const int warp_n = wid >> 2;

    const u16 *Ah_, *Al_, *Bh_, *Bl_;
    if (MODE == 0) { Ah_ = g_ih; Al_ = g_il; Bh_ = g_w0h; Bl_ = g_w0l; }
    else if (MODE == 1) {
        Ah_ = LSEL ? g_x1h : g_x0h; Al_ = LSEL ? g_x1l : g_x0l;
        Bh_ = g_w1h + LSEL * (H_ * 3 * H_); Bl_ = g_w1l + LSEL * (H_ * 3 * H_);
    } else { Ah_ = g_ph; Al_ = g_pl; Bh_ = g_w3h; Bl_ = g_w3l; }

    const int bm = blockIdx.y * 128;
    const int bn = blockIdx.x * 128;
    const int NCH = K >> 5;

    auto issue = [&](int c) {
        const uint32_t stg = sb + (uint32_t)((c & 3) * STG_SZ);
        const int k0 = c << 5;
        #pragma unroll
        for (int it = 0; it < 2; it++) {
            int slot = tid + it * 256;
            int m = slot >> 2, q = slot & 3;
            size_t so = (size_t)(bm + m) * lda + k0 + q * 8;
            uint32_t d = stg + AH_O + m * 80 + q * 16;
            CP16(d, Ah_ + so);
            CP16(d + (AL_O - AH_O), Al_ + so);
        }
        #pragma unroll
        for (int it = 0; it < 2; it++) {
            int slot = tid + it * 256;
            int k = slot >> 4, seg = slot & 15;
            size_t so = (size_t)(k0 + k) * ldbn + bn + seg * 8;
            uint32_t d = stg + BH_O + k * 272 + seg * 16;
            CP16(d, Bh_ + so);
            CP16(d + (BL_O - BH_O), Bl_ + so);
        }
    };

    const int sub = lane >> 3;
    const int l7 = lane & 7;
    const uint32_t a_off = (uint32_t)((warp_m * 32 + (sub & 1) * 8 + l7) * 80
                                      + ((sub >> 1) * 8) * 2);
    const uint32_t b_off = (uint32_t)(((sub & 1) * 8 + l7) * 272
                                      + (warp_n * 64 + (sub >> 1) * 8) * 2);

    float acc[2][8][4];
    #pragma unroll
    for (int mt = 0; mt < 2; mt++)
        #pragma unroll
        for (int nt = 0; nt < 8; nt++)
            #pragma unroll
            for (int q = 0; q < 4; q++) acc[mt][nt][q] = 0.f;

    issue(0); CP_COMMIT;
    issue(1); CP_COMMIT;
    issue(2); CP_COMMIT;

    for (int c = 0; c < NCH; c++) {
        CP_WAIT(2);
        __syncthreads();
        if (c + 3 < NCH) issue(c + 3);
        CP_COMMIT;                       // always commit: ring invariant
        const uint32_t stg = sb + (uint32_t)((c & 3) * STG_SZ);
        #pragma unroll
        for (int ks = 0; ks < 2; ks++) {
            uint32_t ah[2][4], al[2][4], bh[8][2], bl[8][2];
            #pragma unroll
            for (int mt = 0; mt < 2; mt++) {
                uint32_t ad = stg + AH_O + a_off + mt * (16 * 80) + ks * 32;
                LDSM4(ah[mt], ad);
                LDSM4(al[mt], ad + (AL_O - AH_O));
            }
            #pragma unroll
            for (int p = 0; p < 4; p++) {
                uint32_t bd = stg + BH_O + b_off + p * 32 + ks * (16 * 272);
                uint32_t r[4];
                LDSM4T(r, bd);
                bh[2*p][0] = r[0]; bh[2*p][1] = r[1];
                bh[2*p+1][0] = r[2]; bh[2*p+1][1] = r[3];
                LDSM4T(r, bd + (BL_O - BH_O));
                bl[2*p][0] = r[0]; bl[2*p][1] = r[1];
                bl[2*p+1][0] = r[2]; bl[2*p+1][1] = r[3];
            }
            #pragma unroll
            for (int mt = 0; mt < 2; mt++)
                #pragma unroll
                for (int nt = 0; nt < 8; nt++) {
                    MMA16816(acc[mt][nt], ah[mt], bh[nt]);
                    MMA16816(acc[mt][nt], ah[mt], bl[nt]);
                    MMA16816(acc[mt][nt], al[mt], bh[nt]);
                }
        }
    }

    const int g = lane >> 2;
    const int qc = (lane & 3) * 2;
    #pragma unroll
    for (int mt = 0; mt < 2; mt++) {
        const int m0 = bm + warp_m * 32 + mt * 16 + g;
        #pragma unroll
        for (int nt = 0; nt < 8; nt++) {
            const int n = bn + warp_n * 64 + nt * 8 + qc;
            const float* a = acc[mt][nt];
            if (MODE == 0) {
                float b0 = bias[n], b1 = bias[n + 1];
                #pragma unroll
                for (int rr = 0; rr < 2; rr++) {
                    int m = m0 + rr * 8;
                    int bb = m / T_, tt = m - bb * T_;
                    size_t idx = ((size_t)tt * B_ + bb) * H_ + n;
                    float v0 = tanh_fast(a[rr * 2 + 0] + b0);
                    float v1 = tanh_fast(a[rr * 2 + 1] + b1);
                    *(float2*)(g_x0 + idx) = make_float2(v0, v1);
                    float h0 = bf_hif(v0), h1 = bf_hif(v1);
                    *(uint32_t*)(g_x0h + idx) = pack_bf(h0, h1);
                    *(uint32_t*)(g_x0l + idx) = pack_bf(v0 - h0, v1 - h1);
                }
            } else if (MODE == 1) {
                *(float2*)(g_U + (size_t)m0 * (3 * H_) + n) = make_float2(a[0], a[1]);
                *(float2*)(g_U + (size_t)(m0 + 8) * (3 * H_) + n) = make_float2(a[2], a[3]);
            } else {
                #pragma unroll
                for (int rr = 0; rr < 2; rr++) {
                    int m = m0 + rr * 8;
                    #pragma unroll
                    for (int cc = 0; cc < 2; cc++) {
                        int nn = n + cc;
                        float s = sigmoidf_(a[rr * 2 + cc] + bias[nn]);
                        Cparam[(size_t)m * IND_ + nn] =
                            s * extra[(size_t)m * FEAT_ + IND_ + nn];
                    }
                }
            }
        }
    }
}

// ---------------------------------------------------------------------------
// SRU scan: 256 CTAs x 32 threads (one warp), cp.async depth-15 ring.
// L==0 also emits bf16 hi/lo of the output (next GEMM's A operand).
// ---------------------------------------------------------------------------
template<int L>
__global__ void __launch_bounds__(32) sru_scan(const float* __restrict__ v,
                                               const float* __restrict__ bb)
{
    __shared__ float s[4][16][32];
    const float* xin  = (L == 0) ? g_x0 : g_x1;
    float*       xout = (L == 0) ? g_x1 : g_x0;
    const int tid = threadIdx.x;
    const int b = blockIdx.y;
    const int h = blockIdx.x * 32 + tid;

    const float vf = v[h],  vr = v[H_ + h];
    const float bf = bb[h], br = bb[H_ + h];

    auto issue = [&](int u) {
        int slot = u & 15;
        const float* Ub = g_U + ((size_t)u * B_ + b) * (3 * H_) + h;
        const float* Xb = xin + ((size_t)u * B_ + b) * H_ + h;
        CP4(smem_u32(&s[0][slot][tid]), Ub);
        CP4(smem_u32(&s[1][slot][tid]), Ub + H_);
        CP4(smem_u32(&s[2][slot][tid]), Ub + 2 * H_);
        CP4(smem_u32(&s[3][slot][tid]), Xb);
        CP_COMMIT;
    };
    #pragma unroll
    for (int u = 0; u < 15; u++) issue(u);

    float c = 0.f;
    const size_t base = (size_t)b * H_ + h;
    int t = 0;
    for (; t < T_ - 15; t++) {
        CP_WAIT(14);
        int slot = t & 15;
        float xt = s[0][slot][tid], fp = s[1][slot][tid];
        float rp = s[2][slot][tid], xi = s[3][slot][tid];
        float f  = sigmoidf_(fp + vf * c + bf);
        float cn = f * c + (1.f - f) * xt;
        float r  = sigmoidf_(rp + vr * c + br);
        float ho = r * cn + (1.f - r) * xi;
        size_t o = base + (size_t)t * B_ * H_;
        xout[o] = ho;
        if (L == 0) {
            float hh = bf_hif(ho);
            g_x1h[o] = bf_hi(ho);
            g_x1l[o] = bf_hi(ho - hh);
        }
        c = cn;
        issue(t + 15);
    }
    CP_WAIT(0);
    for (; t < T_; t++) {
        int slot = t & 15;
        float xt = s[0][slot][tid], fp = s[1][slot][tid];
        float rp = s[2][slot][tid], xi = s[3][slot][tid];
        float f  = sigmoidf_(fp + vf * c + bf);
        float cn = f * c + (1.f - f) * xt;
        float r  = sigmoidf_(rp + vr * c + br);
        float ho = r * cn + (1.f - r) * xi;
        size_t o = base + (size_t)t * B_ * H_;
        xout[o] = ho;
        if (L == 0) {
            float hh = bf_hif(ho);
            g_x1h[o] = bf_hi(ho);
            g_x1l[o] = bf_hi(ho - hh);
        }
        c = cn;
    }
}

// ---------------------------------------------------------------------------
// Fused Conv2d 6x6 (+bias, tanh) + MaxPool 3x3 s1 p1 -> bf16 hi/lo pool arrays
// ---------------------------------------------------------------------------
__global__ void __launch_bounds__(256) convpool_kernel(const float* __restrict__ ck,
                                                       const float* __restrict__ cb)
{
    __shared__ float xs[23][73];
    __shared__ float cs[18][68];
    __shared__ float sk[KN_ * 36];
    const int tid = threadIdx.x;
    const int h0 = blockIdx.x * 64;
    const int t0 = blockIdx.y * 16;
    const int b  = blockIdx.z;

    for (int i = tid; i < KN_ * 36; i += 256) sk[i] = ck[i];

    for (int idx = tid; idx < 23 * 73; idx += 256) {
        int row = idx / 73, col = idx % 73;
        if (col < 71) {
            int gt = t0 - 4 + row, gh = h0 - 4 + col;
            float val = 0.f;
            if (gt >= 0 && gt < T_ && gh >= 0 && gh < H_)
                val = g_x0[((size_t)gt * B_ + b) * H_ + gh];
            xs[row][col] = val;
        }
    }
    __syncthreads();

    for (int kn = 0; kn < KN_; kn++) {
        const float cbias = cb[kn];
        const float* w = &sk[kn * 36];
        for (int sidx = tid; sidx < 306; sidx += 256) {
            int ci = sidx % 18;
            int cj0 = (sidx / 18) * 4;
            int gt = t0 - 1 + ci;
            float a0 = 0.f, a1 = 0.f, a2 = 0.f, a3 = 0.f;
            #pragma unroll
            for (int i = 0; i < 6; i++) {
                float x9[9];
                #pragma unroll
                for (int j = 0; j < 9; j++) x9[j] = xs[ci + i][cj0 + j];
                #pragma unroll
                for (int j = 0; j < 6; j++) {
                    float wv = w[i * 6 + j];
                    a0 = fmaf(x9[j],     wv, a0);
                    a1 = fmaf(x9[j + 1], wv, a1);
                    a2 = fmaf(x9[j + 2], wv, a2);
                    a3 = fmaf(x9[j + 3], wv, a3);
                }
            }
            bool tv = (gt >= 0 && gt < T_);
            float av[4] = {a0, a1, a2, a3};
            #pragma unroll
            for (int q = 0; q < 4; q++) {
                int cj = cj0 + q;
                if (cj < 66) {
                    int gh = h0 - 1 + cj;
                    cs[ci][cj] = (tv && gh >= 0 && gh < H_)
                               ? tanh_fast(av[q] + cbias) : -1e30f;
                }
            }
        }
        __syncthreads();
        {
            int ti = tid >> 4;
            int hj0 = (tid & 15) * 4;
            int gt = t0 + ti;
            if (gt < T_) {
                float o[4] = {-1e30f, -1e30f, -1e30f, -1e30f};
                #pragma unroll
                for (int r = 0; r < 3; r++) {
                    float c6[6];
                    #pragma unroll
                    for (int j = 0; j < 6; j++) c6[j] = cs[ti + r][hj0 + j];
                    o[0] = fmaxf(o[0], fmaxf(c6[0], fmaxf(c6[1], c6[2])));
                    o[1] = fmaxf(o[1], fmaxf(c6[1], fmaxf(c6[2], c6[3])));
                    o[2] = fmaxf(o[2], fmaxf(c6[2], fmaxf(c6[3], c6[4])));
                    o[3] = fmaxf(o[3], fmaxf(c6[3], fmaxf(c6[4], c6[5])));
                }
                size_t base = (((size_t)b * T_ + gt) * KN_ + kn) * H_ + h0 + hj0;
                ushort4 ph, pl;
                float h0f = bf_hif(o[0]), h1f = bf_hif(o[1]);
                float h2f = bf_hif(o[2]), h3f = bf_hif(o[3]);
                ph = make_ushort4(bf_hi(o[0]), bf_hi(o[1]), bf_hi(o[2]), bf_hi(o[3]));
                pl = make_ushort4(bf_hi(o[0]-h0f), bf_hi(o[1]-h1f),
                                  bf_hi(o[2]-h2f), bf_hi(o[3]-h3f));
                *(ushort4*)&g_ph[base] = ph;
                *(ushort4*)&g_pl[base] = pl;
            }
        }
        __syncthreads();
    }
}

// ---------------------------------------------------------------------------
// Conversion pre-passes
// ---------------------------------------------------------------------------
__global__ void cvt_inputs(const float* __restrict__ inputs)
{
    size_t idx = (size_t)blockIdx.x * 256 + threadIdx.x;
    if (idx >= (size_t)M_ * KPAD_) return;
    int m = (int)(idx / KPAD_), k = (int)(idx % KPAD_);
    float v = (k < FEAT_) ? inputs[(size_t)m * FEAT_ + k] : 0.f;
    float h = bf_hif(v);
    g_ih[idx] = bf_hi(v);
    g_il[idx] = bf_hi(v - h);
}
__global__ void cvt_w_in(const float* __restrict__ W_in)
{
    int idx = blockIdx.x * 256 + threadIdx.x;
    if (idx >= KPAD_ * H_) return;
    int k = idx >> 9, n = idx & 511;
    float v = (k < FEAT_) ? W_in[(size_t)k * H_ + n] : 0.f;
    float h = bf_hif(v);
    g_w0h[idx] = bf_hi(v);
    g_w0l[idx] = bf_hi(v - h);
}
__global__ void cvt_w_rnn(const float* __restrict__ W_rnn)
{
    int idx = blockIdx.x * 256 + threadIdx.x;
    if (idx >= 2 * H_ * 3 * H_) return;
    float v = W_rnn[idx];
    float h = bf_hif(v);
    g_w1h[idx] = bf_hi(v);
    g_w1l[idx] = bf_hi(v - h);
}
__global__ void cvt_w_out(const float* __restrict__ W_out)
{
    int idx = blockIdx.x * 256 + threadIdx.x;
    if (idx >= KN_ * H_ * 256) return;
    int k = idx >> 8, n = idx & 255;
    int kn = k >> 9, hh = k & 511;
    float v = W_out[(size_t)(hh * KN_ + kn) * FEAT_ + IND_ + n];
    float h = bf_hif(v);
    g_w3h[idx] = bf_hi(v);
    g_w3l[idx] = bf_hi(v - h);
}
__global__ void prep_wc(const float* __restrict__ W_out)
{
    int idx = blockIdx.x * 256 + threadIdx.x;
    if (idx < KN_ * H_) {
        int kn = idx >> 9, h = idx & 511;
        g_wc[idx] = W_out[(size_t)(h * KN_ + kn) * FEAT_ + IND_ + 256];
    }
}

// ---------------------------------------------------------------------------
// GEMV for output column 256 (reads bf16 hi/lo pool)
// ---------------------------------------------------------------------------
__global__ void __launch_bounds__(256) gemv_kernel(const float* __restrict__ inputs,
                                                   const float* __restrict__ b_out,
                                                   float* __restrict__ out)
{
    __shared__ float swc[KN_ * H_];
    const int tid = threadIdx.x, wid = tid >> 5, lane = tid & 31;
    float4* s4 = (float4*)swc;
    for (int i = tid; i < (KN_ * H_) / 4; i += 256)
        s4[i] = ((const float4*)g_wc)[i];
    __syncthreads();
    const int m = blockIdx.x * 8 + wid;
    const ushort4* ph = (const ushort4*)(g_ph + (size_t)m * (KN_ * H_));
    const ushort4* pl = (const ushort4*)(g_pl + (size_t)m * (KN_ * H_));
    float s = 0.f;
    for (int i = lane; i < (KN_ * H_) / 4; i += 32) {
        ushort4 hq = ph[i], lq = pl[i];
        float4 w = s4[i];
        s += (bf2f(hq.x) + bf2f(lq.x)) * w.x;
        s += (bf2f(hq.y) + bf2f(lq.y)) * w.y;
        s += (bf2f(hq.z) + bf2f(lq.z)) * w.z;
        s += (bf2f(hq.w) + bf2f(lq.w)) * w.w;
    }
    #pragma unroll
    for (int o = 16; o; o >>= 1) s += __shfl_xor_sync(0xffffffffu, s, o);
    if (lane == 0) {
        float sg = sigmoidf_(s + b_out[IND_ + 256]);
        out[(size_t)m * IND_ + 256] = sg * inputs[(size_t)m * FEAT_ + IND_ + 256];
    }
}

// ---------------------------------------------------------------------------
extern "C" void kernel_launch(void* const* d_in, const int* in_sizes, int n_in,
                              void* d_out, int out_size)
{
    (void)in_sizes; (void)n_in; (void)out_size;
    const float* inputs = (const float*)d_in[0];
    const float* W_in   = (const float*)d_in[1];
    const float* b_in   = (const float*)d_in[2];
    const float* W_rnn  = (const float*)d_in[3];
    const float* v_rnn  = (const float*)d_in[4];
    const float* b_rnn  = (const float*)d_in[5];
    const float* conv_k = (const float*)d_in[6];
    const float* conv_b = (const float*)d_in[7];
    const float* W_out  = (const float*)d_in[8];
    const float* b_out  = (const float*)d_in[9];
    float* out = (float*)d_out;

    cudaFuncSetAttribute(mma_gemm<0,0>, cudaFuncAttributeMaxDynamicSharedMemorySize, GEMM_SMEM);
    cudaFuncSetAttribute(mma_gemm<1,0>, cudaFuncAttributeMaxDynamicSharedMemorySize, GEMM_SMEM);
    cudaFuncSetAttribute(mma_gemm<1,1>, cudaFuncAttributeMaxDynamicSharedMemorySize, GEMM_SMEM);
    cudaFuncSetAttribute(mma_gemm<2,0>, cudaFuncAttributeMaxDynamicSharedMemorySize, GEMM_SMEM);

    // Pre-passes (weights + inputs -> bf16 hi/lo, W_out gathers)
    prep_wc<<<(KN_ * H_ + 255) / 256, 256>>>(W_out);
    cvt_w_in<<<(KPAD_ * H_ + 255) / 256, 256>>>(W_in);
    cvt_w_rnn<<<(2 * H_ * 3 * H_ + 255) / 256, 256>>>(W_rnn);
    cvt_w_out<<<(KN_ * H_ * 256 + 255) / 256, 256>>>(W_out);
    cvt_inputs<<<(int)(((size_t)M_ * KPAD_ + 255) / 256), 256>>>(inputs);

    // Input layer -> g_x0 (fp32 + bf16 hi/lo)
    mma_gemm<0,0><<<dim3(4, 125), 256, GEMM_SMEM>>>(b_in, nullptr, nullptr,
                                                    H_, KPAD_, KPAD_, H_);
    // SRU layer 0
    mma_gemm<1,0><<<dim3(12, 125), 256, GEMM_SMEM>>>(nullptr, nullptr, nullptr,
                                                     3 * H_, H_, H_, 3 * H_);
    sru_scan<0><<<dim3(16, 16), 32>>>(v_rnn, b_rnn);
    // SRU layer 1
    mma_gemm<1,1><<<dim3(12, 125), 256, GEMM_SMEM>>>(nullptr, nullptr, nullptr,
                                                     3 * H_, H_, H_, 3 * H_);
    sru_scan<1><<<dim3(16, 16), 32>>>(v_rnn + 2 * H_, b_rnn + 2 * H_);
    // Fused conv + tanh + maxpool -> bf16 hi/lo pool
    convpool_kernel<<<dim3(8, 63, 16), 256>>>(conv_k, conv_b);
    // Output GEMM (cols 0..255) + sigmoid * inputs
    mma_gemm<2,0><<<dim3(2, 125), 256, GEMM_SMEM>>>(b_out + IND_, inputs, out,
                                                    256, KN_ * H_, KN_ * H_, 256);
    // Output column 256 via GEMV
    gemv_kernel<<<M_ / 8, 256>>>(inputs, b_out, out);
}